// round 12
// baseline (speedup 1.0000x reference)
#include <cuda_runtime.h>

#define B_  16
#define C_  64
#define N_  512
#define T_  128
#define NT_ (N_ * T_)   // 65536

#define ATT_PAD 72      // bf16 elems per att row (bank-conflict-free: 4*gid+ctid)
#define SIG_PAD 132     // f32 elems per sig row  (bank-conflict-free: 8*ctid+gid)

// Scratch (device globals — no allocation allowed in kernel_launch)
__device__ float g_k[B_ * C_ * T_];                         // [16,64,128]
__device__ unsigned short g_att_hi[B_ * C_ * ATT_PAD];      // bf16 hi (truncated)
__device__ unsigned short g_att_lo[B_ * C_ * ATT_PAD];      // bf16 lo (rn residual)

// bf16 mma: D(16x8) += A(16x16,row) * B(16x8,col), fp32 accum
#define MMA_BF16(d0,d1,d2,d3, a0,a1,a2,a3, b0,b1)                              \
    asm volatile("mma.sync.aligned.m16n8k16.row.col.f32.bf16.bf16.f32 "        \
        "{%0,%1,%2,%3}, {%4,%5,%6,%7}, {%8,%9}, {%0,%1,%2,%3};"                \
        : "+f"(d0), "+f"(d1), "+f"(d2), "+f"(d3)                               \
        : "r"(a0), "r"(a1), "r"(a2), "r"(a3), "r"(b0), "r"(b1))

// ---------------------------------------------------------------------------
// Kernel 1: k[b,c,t] = sum_n signals[b,c,n,t] * alpha[n]   (at LTS cap)
// ---------------------------------------------------------------------------
__global__ void __launch_bounds__(256) k_reduce_kernel(
    const float* __restrict__ sig, const float* __restrict__ alpha)
{
    __shared__ float  al[N_];
    __shared__ float4 sred[8][32];
    const int tid = threadIdx.x;
    #pragma unroll
    for (int i = tid; i < N_; i += 256) al[i] = alpha[i];
    __syncthreads();

    const int bc = blockIdx.x;
    const int q  = tid & 31;
    const int g  = tid >> 5;

    const float4* p = (const float4*)(sig + (size_t)bc * NT_) + g * 32 + q;

    float4 acc = make_float4(0.f, 0.f, 0.f, 0.f);
    #pragma unroll 8
    for (int m = 0; m < 64; m++) {
        float  av = al[g + 8 * m];
        float4 v  = p[(size_t)m * 256];
        acc.x = fmaf(v.x, av, acc.x);
        acc.y = fmaf(v.y, av, acc.y);
        acc.z = fmaf(v.z, av, acc.z);
        acc.w = fmaf(v.w, av, acc.w);
    }
    sred[g][q] = acc;
    __syncthreads();

    if (tid < 32) {
        float4 s = sred[0][tid];
        #pragma unroll
        for (int gg = 1; gg < 8; gg++) {
            float4 v = sred[gg][tid];
            s.x += v.x; s.y += v.y; s.z += v.z; s.w += v.w;
        }
        ((float4*)(g_k + bc * T_))[tid] = s;
    }
}

// ---------------------------------------------------------------------------
// Kernel 2: scores -> softmax -> att, emitted PRE-SPLIT as bf16 hi/lo in the
// padded [c][72] layout k_mix's A fragments want. hi = truncation (exact bf16,
// exact f32 residual), lo = rn(residual).
// ---------------------------------------------------------------------------
__global__ void __launch_bounds__(256) k_att_kernel(const float* __restrict__ Wc)
{
    __shared__ float kk[C_ * (T_ + 1)];
    __shared__ float srow[8][T_ + 4];

    const int b    = blockIdx.x >> 3;
    const int rgrp = blockIdx.x & 7;
    const int tid  = threadIdx.x;
    const int lane = tid & 31;
    const int w    = tid >> 5;

    const float* kb = g_k + b * (C_ * T_);
    for (int i = tid; i < C_ * T_; i += 256) {
        int c = i >> 7, t = i & 127;
        kk[c * (T_ + 1) + t] = kb[i];
    }
    __syncthreads();

    const int c = rgrp * 8 + w;

    float kw0 = 0.f, kw1 = 0.f, kw2 = 0.f, kw3 = 0.f;
    const float4* W4 = (const float4*)Wc;
    #pragma unroll 4
    for (int t = 0; t < T_; t++) {
        float4 wv = __ldg(&W4[t * 32 + lane]);
        float kc = kk[c * (T_ + 1) + t];
        kw0 = fmaf(kc, wv.x, kw0);
        kw1 = fmaf(kc, wv.y, kw1);
        kw2 = fmaf(kc, wv.z, kw2);
        kw3 = fmaf(kc, wv.w, kw3);
    }
    srow[w][lane * 4 + 0] = kw0;
    srow[w][lane * 4 + 1] = kw1;
    srow[w][lane * 4 + 2] = kw2;
    srow[w][lane * 4 + 3] = kw3;
    __syncwarp();

    float s0 = 0.f, s1 = 0.f;
    #pragma unroll 4
    for (int s = 0; s < T_; s++) {
        float v = srow[w][s];
        s0 = fmaf(v, kk[lane * (T_ + 1) + s], s0);
        s1 = fmaf(v, kk[(lane + 32) * (T_ + 1) + s], s1);
    }
    __syncwarp();

    float m = fmaxf(s0, s1);
    #pragma unroll
    for (int o = 16; o > 0; o >>= 1) m = fmaxf(m, __shfl_xor_sync(0xffffffffu, m, o));
    float e0 = __expf(s0 - m), e1 = __expf(s1 - m);
    float sum = e0 + e1;
    #pragma unroll
    for (int o = 16; o > 0; o >>= 1) sum += __shfl_xor_sync(0xffffffffu, sum, o);
    float inv = 1.f / sum;
    float v0 = e0 * inv, v1 = e1 * inv;

    unsigned short* ah = g_att_hi + (b * C_ + c) * ATT_PAD;
    unsigned short* al = g_att_lo + (b * C_ + c) * ATT_PAD;

    unsigned u0 = __float_as_uint(v0);
    unsigned u1 = __float_as_uint(v1);
    float l0 = v0 - __uint_as_float(u0 & 0xffff0000u);
    float l1 = v1 - __uint_as_float(u1 & 0xffff0000u);
    unsigned short lb0, lb1;
    asm("cvt.rn.bf16.f32 %0, %1;" : "=h"(lb0) : "f"(l0));
    asm("cvt.rn.bf16.f32 %0, %1;" : "=h"(lb1) : "f"(l1));
    ah[lane]      = (unsigned short)(u0 >> 16);
    ah[lane + 32] = (unsigned short)(u1 >> 16);
    al[lane]      = lb0;
    al[lane + 32] = lb1;
    // pad columns 64..71 left untouched (never consumed by MMA fragments)
}

// ---------------------------------------------------------------------------
// Kernel 3: out[b] = att[b](64x64) @ sig[b](64x65536), bf16 m16n8k16 MMA,
// 3-term split (AhBh + AhBl + AlBh). Staging is raw-f32 sig + tiny bf16 att
// copies; all splitting happens on fragments in registers (PRMT/LOP3/FSUB).
// smem 51 KB -> 4 blocks/SM.
// ---------------------------------------------------------------------------
__global__ void __launch_bounds__(128) k_mix_kernel(
    const float* __restrict__ sig, float* __restrict__ out)
{
    extern __shared__ __align__(16) char smraw[];
    float* sS = (float*)smraw;                                   // [64][132] f32
    unsigned short* aHi = (unsigned short*)(smraw + 64 * SIG_PAD * 4);
    unsigned short* aLo = aHi + C_ * ATT_PAD;

    const int tid = threadIdx.x;
    const int b   = blockIdx.y;
    const int j0  = blockIdx.x * 128;

    // stage pre-split att (9216 B each, L2-hot)
    {
        const int4* gh = (const int4*)(g_att_hi + b * C_ * ATT_PAD);
        const int4* gl = (const int4*)(g_att_lo + b * C_ * ATT_PAD);
        int4* sh = (int4*)aHi;
        int4* sl = (int4*)aLo;
        #pragma unroll
        for (int i = tid; i < C_ * ATT_PAD / 8; i += 128) {
            sh[i] = gh[i];
            sl[i] = gl[i];
        }
    }

    // stage sig tile raw [64 i][128 j]
    {
        const float* sb = sig + (size_t)b * (C_ * NT_) + j0;
        #pragma unroll
        for (int idx = tid; idx < 64 * 32; idx += 128) {
            int row = idx >> 5, q = idx & 31;
            ((float4*)(sS + row * SIG_PAD))[q] =
                *(const float4*)(sb + (size_t)row * NT_ + q * 4);
        }
    }
    __syncthreads();

    const int lane = tid & 31;
    const int w    = tid >> 5;
    const int ctid = lane & 3;
    const int gid  = lane >> 2;

    float acc[4][4][4];
    #pragma unroll
    for (int m = 0; m < 4; m++)
        #pragma unroll
        for (int n = 0; n < 4; n++)
            acc[m][n][0] = acc[m][n][1] = acc[m][n][2] = acc[m][n][3] = 0.f;

    #pragma unroll
    for (int kstep = 0; kstep < 4; kstep++) {
        const int k0 = kstep * 16;

        // B fragments: 4 n-tiles, hi (PRMT-pack of truncations) + lo (residual)
        unsigned bh[4][2], bl[4][2];
        #pragma unroll
        for (int n = 0; n < 4; n++) {
            const float* col = sS + (w * 32 + n * 8 + gid);
            float f0 = col[(k0 + 2 * ctid)     * SIG_PAD];
            float f1 = col[(k0 + 2 * ctid + 1) * SIG_PAD];
            float f2 = col[(k0 + 2 * ctid + 8) * SIG_PAD];
            float f3 = col[(k0 + 2 * ctid + 9) * SIG_PAD];
            bh[n][0] = __byte_perm(__float_as_uint(f0), __float_as_uint(f1), 0x7632);
            bh[n][1] = __byte_perm(__float_as_uint(f2), __float_as_uint(f3), 0x7632);
            float l0 = f0 - __uint_as_float(__float_as_uint(f0) & 0xffff0000u);
            float l1 = f1 - __uint_as_float(__float_as_uint(f1) & 0xffff0000u);
            float l2 = f2 - __uint_as_float(__float_as_uint(f2) & 0xffff0000u);
            float l3 = f3 - __uint_as_float(__float_as_uint(f3) & 0xffff0000u);
            asm("cvt.rn.bf16x2.f32 %0, %1, %2;" : "=r"(bl[n][0]) : "f"(l1), "f"(l0));
            asm("cvt.rn.bf16x2.f32 %0, %1, %2;" : "=r"(bl[n][1]) : "f"(l3), "f"(l2));
        }

        #pragma unroll
        for (int m = 0; m < 4; m++) {
            const int c0 = m * 16 + gid;
            const int i0 = c0 * ATT_PAD + k0 + 2 * ctid;
            const int i1 = (c0 + 8) * ATT_PAD + k0 + 2 * ctid;
            unsigned ah0 = *(const unsigned*)(aHi + i0);
            unsigned ah1 = *(const unsigned*)(aHi + i1);
            unsigned ah2 = *(const unsigned*)(aHi + i0 + 8);
            unsigned ah3 = *(const unsigned*)(aHi + i1 + 8);
            unsigned al0 = *(const unsigned*)(aLo + i0);
            unsigned al1 = *(const unsigned*)(aLo + i1);
            unsigned al2 = *(const unsigned*)(aLo + i0 + 8);
            unsigned al3 = *(const unsigned*)(aLo + i1 + 8);
            #pragma unroll
            for (int n = 0; n < 4; n++) {
                MMA_BF16(acc[m][n][0], acc[m][n][1], acc[m][n][2], acc[m][n][3],
                         ah0, ah1, ah2, ah3, bh[n][0], bh[n][1]);
                MMA_BF16(acc[m][n][0], acc[m][n][1], acc[m][n][2], acc[m][n][3],
                         ah0, ah1, ah2, ah3, bl[n][0], bl[n][1]);
                MMA_BF16(acc[m][n][0], acc[m][n][1], acc[m][n][2], acc[m][n][3],
                         al0, al1, al2, al3, bh[n][0], bh[n][1]);
            }
        }
    }

    // epilogue: d0/d1 -> (c, j..j+1), d2/d3 -> (c+8, j..j+1)
    #pragma unroll
    for (int m = 0; m < 4; m++) {
        const int c = m * 16 + gid;
        #pragma unroll
        for (int n = 0; n < 4; n++) {
            const int j = j0 + w * 32 + n * 8 + ctid * 2;
            float* p0 = out + ((size_t)(b * C_ + c)) * NT_ + j;
            *(float2*)p0 = make_float2(acc[m][n][0], acc[m][n][1]);
            *(float2*)(p0 + (size_t)8 * NT_) = make_float2(acc[m][n][2], acc[m][n][3]);
        }
    }
}

// ---------------------------------------------------------------------------
extern "C" void kernel_launch(void* const* d_in, const int* in_sizes, int n_in,
                              void* d_out, int out_size)
{
    const float* sig   = (const float*)d_in[0];   // [16,64,512,128]
    const float* Wc    = (const float*)d_in[1];   // [128,128]
    const float* alpha = (const float*)d_in[2];   // [512]
    float* out = (float*)d_out;

    const int smem_mix = 64 * SIG_PAD * 4 + 2 * C_ * ATT_PAD * 2;  // 52224 B
    cudaFuncSetAttribute(k_mix_kernel,
                         cudaFuncAttributeMaxDynamicSharedMemorySize, smem_mix);

    k_reduce_kernel<<<B_ * C_, 256>>>(sig, alpha);
    k_att_kernel<<<B_ * 8, 256>>>(Wc);
    dim3 g3(NT_ / 128, B_);
    k_mix_kernel<<<g3, 128, smem_mix>>>(sig, out);
}

// round 13
// speedup vs baseline: 1.0015x; 1.0015x over previous
#include <cuda_runtime.h>

#define B_  16
#define C_  64
#define N_  512
#define T_  128
#define NT_ (N_ * T_)   // 65536

#define ATT_PAD 72      // bf16 elems per att row (bank-conflict-free: 4*gid+ctid)
#define SIG_PAD 132     // f32 elems per sig row  (bank-conflict-free: 8*ctid+gid)

// Scratch (device globals — no allocation allowed in kernel_launch)
__device__ float g_k[B_ * C_ * T_];                         // [16,64,128]
__device__ unsigned short g_att_hi[B_ * C_ * ATT_PAD];      // bf16 hi (truncated)
__device__ unsigned short g_att_lo[B_ * C_ * ATT_PAD];      // bf16 lo (rn residual)

// bf16 mma: D(16x8) += A(16x16,row) * B(16x8,col), fp32 accum
#define MMA_BF16(d0,d1,d2,d3, a0,a1,a2,a3, b0,b1)                              \
    asm volatile("mma.sync.aligned.m16n8k16.row.col.f32.bf16.bf16.f32 "        \
        "{%0,%1,%2,%3}, {%4,%5,%6,%7}, {%8,%9}, {%0,%1,%2,%3};"                \
        : "+f"(d0), "+f"(d1), "+f"(d2), "+f"(d3)                               \
        : "r"(a0), "r"(a1), "r"(a2), "r"(a3), "r"(b0), "r"(b1))

// ---------------------------------------------------------------------------
// Kernel 1: k[b,c,t] = sum_n signals[b,c,n,t] * alpha[n]   (at LTS cap)
// ---------------------------------------------------------------------------
__global__ void __launch_bounds__(256) k_reduce_kernel(
    const float* __restrict__ sig, const float* __restrict__ alpha)
{
    __shared__ float  al[N_];
    __shared__ float4 sred[8][32];
    const int tid = threadIdx.x;
    #pragma unroll
    for (int i = tid; i < N_; i += 256) al[i] = alpha[i];
    __syncthreads();

    const int bc = blockIdx.x;
    const int q  = tid & 31;
    const int g  = tid >> 5;

    const float4* p = (const float4*)(sig + (size_t)bc * NT_) + g * 32 + q;

    float4 acc = make_float4(0.f, 0.f, 0.f, 0.f);
    #pragma unroll 8
    for (int m = 0; m < 64; m++) {
        float  av = al[g + 8 * m];
        float4 v  = p[(size_t)m * 256];
        acc.x = fmaf(v.x, av, acc.x);
        acc.y = fmaf(v.y, av, acc.y);
        acc.z = fmaf(v.z, av, acc.z);
        acc.w = fmaf(v.w, av, acc.w);
    }
    sred[g][q] = acc;
    __syncthreads();

    if (tid < 32) {
        float4 s = sred[0][tid];
        #pragma unroll
        for (int gg = 1; gg < 8; gg++) {
            float4 v = sred[gg][tid];
            s.x += v.x; s.y += v.y; s.z += v.z; s.w += v.w;
        }
        ((float4*)(g_k + bc * T_))[tid] = s;
    }
}

// ---------------------------------------------------------------------------
// Kernel 2: scores -> softmax -> att, emitted PRE-SPLIT as bf16 hi/lo in the
// padded [c][72] layout k_mix's A fragments want. hi = truncation (exact bf16,
// exact f32 residual), lo = rn(residual).
// ---------------------------------------------------------------------------
__global__ void __launch_bounds__(256) k_att_kernel(const float* __restrict__ Wc)
{
    __shared__ float kk[C_ * (T_ + 1)];
    __shared__ float srow[8][T_ + 4];

    const int b    = blockIdx.x >> 3;
    const int rgrp = blockIdx.x & 7;
    const int tid  = threadIdx.x;
    const int lane = tid & 31;
    const int w    = tid >> 5;

    const float* kb = g_k + b * (C_ * T_);
    for (int i = tid; i < C_ * T_; i += 256) {
        int c = i >> 7, t = i & 127;
        kk[c * (T_ + 1) + t] = kb[i];
    }
    __syncthreads();

    const int c = rgrp * 8 + w;

    float kw0 = 0.f, kw1 = 0.f, kw2 = 0.f, kw3 = 0.f;
    const float4* W4 = (const float4*)Wc;
    #pragma unroll 4
    for (int t = 0; t < T_; t++) {
        float4 wv = __ldg(&W4[t * 32 + lane]);
        float kc = kk[c * (T_ + 1) + t];
        kw0 = fmaf(kc, wv.x, kw0);
        kw1 = fmaf(kc, wv.y, kw1);
        kw2 = fmaf(kc, wv.z, kw2);
        kw3 = fmaf(kc, wv.w, kw3);
    }
    srow[w][lane * 4 + 0] = kw0;
    srow[w][lane * 4 + 1] = kw1;
    srow[w][lane * 4 + 2] = kw2;
    srow[w][lane * 4 + 3] = kw3;
    __syncwarp();

    float s0 = 0.f, s1 = 0.f;
    #pragma unroll 4
    for (int s = 0; s < T_; s++) {
        float v = srow[w][s];
        s0 = fmaf(v, kk[lane * (T_ + 1) + s], s0);
        s1 = fmaf(v, kk[(lane + 32) * (T_ + 1) + s], s1);
    }
    __syncwarp();

    float m = fmaxf(s0, s1);
    #pragma unroll
    for (int o = 16; o > 0; o >>= 1) m = fmaxf(m, __shfl_xor_sync(0xffffffffu, m, o));
    float e0 = __expf(s0 - m), e1 = __expf(s1 - m);
    float sum = e0 + e1;
    #pragma unroll
    for (int o = 16; o > 0; o >>= 1) sum += __shfl_xor_sync(0xffffffffu, sum, o);
    float inv = 1.f / sum;
    float v0 = e0 * inv, v1 = e1 * inv;

    unsigned short* ah = g_att_hi + (b * C_ + c) * ATT_PAD;
    unsigned short* al = g_att_lo + (b * C_ + c) * ATT_PAD;

    unsigned u0 = __float_as_uint(v0);
    unsigned u1 = __float_as_uint(v1);
    float l0 = v0 - __uint_as_float(u0 & 0xffff0000u);
    float l1 = v1 - __uint_as_float(u1 & 0xffff0000u);
    unsigned short lb0, lb1;
    asm("cvt.rn.bf16.f32 %0, %1;" : "=h"(lb0) : "f"(l0));
    asm("cvt.rn.bf16.f32 %0, %1;" : "=h"(lb1) : "f"(l1));
    ah[lane]      = (unsigned short)(u0 >> 16);
    ah[lane + 32] = (unsigned short)(u1 >> 16);
    al[lane]      = lb0;
    al[lane + 32] = lb1;
    // pad columns 64..71 left untouched (never consumed by MMA fragments)
}

// ---------------------------------------------------------------------------
// Kernel 3: out[b] = att[b](64x64) @ sig[b](64x65536), bf16 m16n8k16 MMA,
// 3-term split (AhBh + AhBl + AlBh). Staging is raw-f32 sig + tiny bf16 att
// copies; all splitting happens on fragments in registers (PRMT/LOP3/FSUB).
// smem 51 KB -> 4 blocks/SM.
// ---------------------------------------------------------------------------
__global__ void __launch_bounds__(128) k_mix_kernel(
    const float* __restrict__ sig, float* __restrict__ out)
{
    extern __shared__ __align__(16) char smraw[];
    float* sS = (float*)smraw;                                   // [64][132] f32
    unsigned short* aHi = (unsigned short*)(smraw + 64 * SIG_PAD * 4);
    unsigned short* aLo = aHi + C_ * ATT_PAD;

    const int tid = threadIdx.x;
    const int b   = blockIdx.y;
    const int j0  = blockIdx.x * 128;

    // stage pre-split att (9216 B each, L2-hot)
    {
        const int4* gh = (const int4*)(g_att_hi + b * C_ * ATT_PAD);
        const int4* gl = (const int4*)(g_att_lo + b * C_ * ATT_PAD);
        int4* sh = (int4*)aHi;
        int4* sl = (int4*)aLo;
        #pragma unroll
        for (int i = tid; i < C_ * ATT_PAD / 8; i += 128) {
            sh[i] = gh[i];
            sl[i] = gl[i];
        }
    }

    // stage sig tile raw [64 i][128 j]
    {
        const float* sb = sig + (size_t)b * (C_ * NT_) + j0;
        #pragma unroll
        for (int idx = tid; idx < 64 * 32; idx += 128) {
            int row = idx >> 5, q = idx & 31;
            ((float4*)(sS + row * SIG_PAD))[q] =
                *(const float4*)(sb + (size_t)row * NT_ + q * 4);
        }
    }
    __syncthreads();

    const int lane = tid & 31;
    const int w    = tid >> 5;
    const int ctid = lane & 3;
    const int gid  = lane >> 2;

    float acc[4][4][4];
    #pragma unroll
    for (int m = 0; m < 4; m++)
        #pragma unroll
        for (int n = 0; n < 4; n++)
            acc[m][n][0] = acc[m][n][1] = acc[m][n][2] = acc[m][n][3] = 0.f;

    #pragma unroll
    for (int kstep = 0; kstep < 4; kstep++) {
        const int k0 = kstep * 16;

        // B fragments: 4 n-tiles, hi (PRMT-pack of truncations) + lo (residual)
        unsigned bh[4][2], bl[4][2];
        #pragma unroll
        for (int n = 0; n < 4; n++) {
            const float* col = sS + (w * 32 + n * 8 + gid);
            float f0 = col[(k0 + 2 * ctid)     * SIG_PAD];
            float f1 = col[(k0 + 2 * ctid + 1) * SIG_PAD];
            float f2 = col[(k0 + 2 * ctid + 8) * SIG_PAD];
            float f3 = col[(k0 + 2 * ctid + 9) * SIG_PAD];
            bh[n][0] = __byte_perm(__float_as_uint(f0), __float_as_uint(f1), 0x7632);
            bh[n][1] = __byte_perm(__float_as_uint(f2), __float_as_uint(f3), 0x7632);
            float l0 = f0 - __uint_as_float(__float_as_uint(f0) & 0xffff0000u);
            float l1 = f1 - __uint_as_float(__float_as_uint(f1) & 0xffff0000u);
            float l2 = f2 - __uint_as_float(__float_as_uint(f2) & 0xffff0000u);
            float l3 = f3 - __uint_as_float(__float_as_uint(f3) & 0xffff0000u);
            asm("cvt.rn.bf16x2.f32 %0, %1, %2;" : "=r"(bl[n][0]) : "f"(l1), "f"(l0));
            asm("cvt.rn.bf16x2.f32 %0, %1, %2;" : "=r"(bl[n][1]) : "f"(l3), "f"(l2));
        }

        #pragma unroll
        for (int m = 0; m < 4; m++) {
            const int c0 = m * 16 + gid;
            const int i0 = c0 * ATT_PAD + k0 + 2 * ctid;
            const int i1 = (c0 + 8) * ATT_PAD + k0 + 2 * ctid;
            unsigned ah0 = *(const unsigned*)(aHi + i0);
            unsigned ah1 = *(const unsigned*)(aHi + i1);
            unsigned ah2 = *(const unsigned*)(aHi + i0 + 8);
            unsigned ah3 = *(const unsigned*)(aHi + i1 + 8);
            unsigned al0 = *(const unsigned*)(aLo + i0);
            unsigned al1 = *(const unsigned*)(aLo + i1);
            unsigned al2 = *(const unsigned*)(aLo + i0 + 8);
            unsigned al3 = *(const unsigned*)(aLo + i1 + 8);
            #pragma unroll
            for (int n = 0; n < 4; n++) {
                MMA_BF16(acc[m][n][0], acc[m][n][1], acc[m][n][2], acc[m][n][3],
                         ah0, ah1, ah2, ah3, bh[n][0], bh[n][1]);
                MMA_BF16(acc[m][n][0], acc[m][n][1], acc[m][n][2], acc[m][n][3],
                         ah0, ah1, ah2, ah3, bl[n][0], bl[n][1]);
                MMA_BF16(acc[m][n][0], acc[m][n][1], acc[m][n][2], acc[m][n][3],
                         al0, al1, al2, al3, bh[n][0], bh[n][1]);
            }
        }
    }

    // epilogue: d0/d1 -> (c, j..j+1), d2/d3 -> (c+8, j..j+1)
    #pragma unroll
    for (int m = 0; m < 4; m++) {
        const int c = m * 16 + gid;
        #pragma unroll
        for (int n = 0; n < 4; n++) {
            const int j = j0 + w * 32 + n * 8 + ctid * 2;
            float* p0 = out + ((size_t)(b * C_ + c)) * NT_ + j;
            *(float2*)p0 = make_float2(acc[m][n][0], acc[m][n][1]);
            *(float2*)(p0 + (size_t)8 * NT_) = make_float2(acc[m][n][2], acc[m][n][3]);
        }
    }
}

// ---------------------------------------------------------------------------
extern "C" void kernel_launch(void* const* d_in, const int* in_sizes, int n_in,
                              void* d_out, int out_size)
{
    const float* sig   = (const float*)d_in[0];   // [16,64,512,128]
    const float* Wc    = (const float*)d_in[1];   // [128,128]
    const float* alpha = (const float*)d_in[2];   // [512]
    float* out = (float*)d_out;

    const int smem_mix = 64 * SIG_PAD * 4 + 2 * C_ * ATT_PAD * 2;  // 52224 B
    cudaFuncSetAttribute(k_mix_kernel,
                         cudaFuncAttributeMaxDynamicSharedMemorySize, smem_mix);

    k_reduce_kernel<<<B_ * C_, 256>>>(sig, alpha);
    k_att_kernel<<<B_ * 8, 256>>>(Wc);
    dim3 g3(NT_ / 128, B_);
    k_mix_kernel<<<g3, 128, smem_mix>>>(sig, out);
}